// round 5
// baseline (speedup 1.0000x reference)
#include <cuda_runtime.h>

// Aggregation buffer: agg[dst] = sum_e w_e * x_src[src_e]  (100000 x 64 f32).
// __device__ global per the allocation-free rule; 16B-aligned (LDG.128 /
// RED.128 targets).
static __device__ __align__(16) float g_agg[100000 * 64];

// Edge-index dtype flag: 1 = int64, 0 = int32. Set by detect kernel each call.
static __device__ int g_idx_is64;

// ---------------------------------------------------------------------------
// f32x2 packed-math helpers (Blackwell): one inst = 2 fp32 FMAs.
// ---------------------------------------------------------------------------
#define FMA_F32X2(d, a, b, c) \
    asm("fma.rn.f32x2 %0, %1, %2, %3;" : "=l"(d) : "l"(a), "l"(b), "l"(c))
#define PACK_F32X2(out, lo, hi) \
    asm("mov.b64 %0, {%1, %2};" : "=l"(out) : "r"(lo), "r"(hi))
#define UNPACK_F32X2(lo, hi, in) \
    asm("mov.b64 {%0, %1}, %2;" : "=r"(lo), "=r"(hi) : "l"(in))

// ---------------------------------------------------------------------------
// Detect whether edge indices are int64 or int32 (JAX demotes int64->int32
// when x64 is disabled). Sampling the first E int64 slots is in-bounds under
// BOTH interpretations. Int32 pairs read as int64 have random high words ->
// out of [0, n_src) with overwhelming probability.
// ---------------------------------------------------------------------------
__global__ void detect_idx_dtype_kernel(const long long* __restrict__ ei,
                                        int E, int n_src)
{
    if (threadIdx.x != 0 || blockIdx.x != 0) return;
    bool ok64 = true;
    int stride = E > 16 ? E / 16 : 1;
    for (int i = 0; i < 16; i++) {
        long long idx = (long long)i * stride;
        if (idx >= E) break;
        long long v = ei[idx];
        if (v < 0 || v >= n_src) { ok64 = false; break; }
    }
    g_idx_is64 = ok64 ? 1 : 0;
}

// ---------------------------------------------------------------------------
// Edge scatter in INPUT space: g_agg[dst] += x_src[src] * w  (64 floats).
// 16 lanes per edge-group; each thread owns one float4 slot of 4 consecutive
// edges -> 4 independent L2 gathers in flight, then 4 vector REDs.
// ---------------------------------------------------------------------------
__global__ void __launch_bounds__(256) scatter_kernel(
    const float* __restrict__ xsrc,
    const void* __restrict__ ei_raw,    // [2, E]: src row then dst row
    const float* __restrict__ ew,       // [E]
    int E)
{
    const long long t = (long long)blockIdx.x * blockDim.x + threadIdx.x;
    const int lane = (int)(t & 15);
    const long long e0 = (t >> 4) * 4;
    if (e0 >= E) return;
    const int n = (E - e0 >= 4) ? 4 : (int)(E - e0);

    long long s[4], d[4];
    float w[4];
    if (g_idx_is64) {
        const long long* ei = (const long long*)ei_raw;
        #pragma unroll
        for (int i = 0; i < 4; i++) if (i < n) {
            s[i] = ei[e0 + i];
            d[i] = ei[(long long)E + e0 + i];
        }
    } else {
        const int* ei = (const int*)ei_raw;
        #pragma unroll
        for (int i = 0; i < 4; i++) if (i < n) {
            s[i] = ei[e0 + i];
            d[i] = ei[(long long)E + e0 + i];
        }
    }
    #pragma unroll
    for (int i = 0; i < 4; i++) if (i < n) w[i] = ew[e0 + i];

    float4 v[4];
    #pragma unroll
    for (int i = 0; i < 4; i++) if (i < n)
        v[i] = *(const float4*)(xsrc + s[i] * 64 + lane * 4);

    #pragma unroll
    for (int i = 0; i < 4; i++) if (i < n) {
        const float wi = w[i];
        float4 vv = v[i];
        vv.x *= wi; vv.y *= wi; vv.z *= wi; vv.w *= wi;
        float* dst = g_agg + d[i] * 64 + lane * 4;
        asm volatile("red.global.add.v4.f32 [%0], {%1, %2, %3, %4};"
                     :: "l"(dst), "f"(vv.x), "f"(vv.y), "f"(vv.z), "f"(vv.w)
                     : "memory");
    }
}

// ---------------------------------------------------------------------------
// Fused GEMM:  out = x_dst @ W_self^T + g_agg @ W_nei^T + b     (N x 64)
// K=128 logically (two 64-K halves staged sequentially).
// Block = 256 threads (tx = tid&7 col-octet, ty = tid>>3 row slot),
// block tile 256 rows x 64 cols, thread tile 8 rows x 8 cols (4 f32x2 pairs).
// W staged transposed [k][c] with even/odd chunk de-interleave so each
// LDS.128 hits 8 distinct bank groups; Xs padded to 68 so the 4 distinct
// row addresses per warp land on distinct bank groups.
// ---------------------------------------------------------------------------
__global__ void __launch_bounds__(256) fused_gemm_kernel(
    const float* __restrict__ Xd,     // x_dst  [N,64]
    const float* __restrict__ Wself,  // [64,64]
    const float* __restrict__ Wnei,   // [64,64]
    const float* __restrict__ bias,   // [64]
    float* __restrict__ out, int N)
{
    __shared__ __align__(16) float Xs[256][68];
    __shared__ __align__(16) float Wt[128][64];  // [k + 64*half][perm(c)]

    const int tid = threadIdx.x;
    const int tx = tid & 7;       // col octet: cols 8tx .. 8tx+7
    const int ty = tid >> 3;      // 0..31, rows ty + 32*i
    const int rowbase = blockIdx.x * 256;

    // ---- stage Wt (both matrices), transposed + chunk-permuted ----
    // logical col c -> chunk cq=c>>2; physical chunk = (cq>>1) + (cq&1)*8
    #pragma unroll
    for (int m = 0; m < 2; m++) {
        const float* Wm = m ? Wnei : Wself;
        #pragma unroll
        for (int i = 0; i < 4; i++) {
            int f  = tid + i * 256;        // float4 id 0..1023
            int c  = f >> 4;               // 0..63
            int k4 = f & 15;
            float4 v = *(const float4*)(Wm + c * 64 + k4 * 4);
            int cq   = c >> 2;
            int pcol = ((cq >> 1) + (cq & 1) * 8) * 4 + (c & 3);
            Wt[m * 64 + k4 * 4 + 0][pcol] = v.x;
            Wt[m * 64 + k4 * 4 + 1][pcol] = v.y;
            Wt[m * 64 + k4 * 4 + 2][pcol] = v.z;
            Wt[m * 64 + k4 * 4 + 3][pcol] = v.w;
        }
    }

    // ---- init accumulators with bias pairs ----
    unsigned long long acc[8][4];
    {
        float4 b0 = *(const float4*)(bias + 8 * tx);
        float4 b1 = *(const float4*)(bias + 8 * tx + 4);
        unsigned long long bp[4];
        PACK_F32X2(bp[0], __float_as_uint(b0.x), __float_as_uint(b0.y));
        PACK_F32X2(bp[1], __float_as_uint(b0.z), __float_as_uint(b0.w));
        PACK_F32X2(bp[2], __float_as_uint(b1.x), __float_as_uint(b1.y));
        PACK_F32X2(bp[3], __float_as_uint(b1.z), __float_as_uint(b1.w));
        #pragma unroll
        for (int i = 0; i < 8; i++)
            #pragma unroll
            for (int p = 0; p < 4; p++) acc[i][p] = bp[p];
    }

    const float* g_agg_p = g_agg;   // device-global base

    #pragma unroll 1
    for (int h = 0; h < 2; h++) {
        const float* Xsrc = h ? (g_agg_p) : Xd;
        __syncthreads();   // Wt ready (h==0) / Xs consumers done (h==1)
        // ---- stage Xs: 256 rows x 64 cols, 16 float4 per thread ----
        #pragma unroll
        for (int i = 0; i < 16; i++) {
            int f  = tid + i * 256;         // 0..4095
            int r  = f >> 4;
            int k4 = f & 15;
            int gr = rowbase + r;
            float4 v = make_float4(0.f, 0.f, 0.f, 0.f);
            if (gr < N) v = *(const float4*)(Xsrc + (size_t)gr * 64 + k4 * 4);
            *(float4*)&Xs[r][k4 * 4] = v;
        }
        __syncthreads();

        #pragma unroll
        for (int kq = 0; kq < 16; kq++) {
            // x rows for this 4-k chunk
            float4 xv[8];
            #pragma unroll
            for (int i = 0; i < 8; i++)
                xv[i] = *(const float4*)&Xs[ty + 32 * i][kq * 4];

            #pragma unroll
            for (int j = 0; j < 4; j++) {   // k within chunk
                const int krow = h * 64 + kq * 4 + j;
                float4 w0 = *(const float4*)&Wt[krow][tx * 4];        // cols 8tx..+3
                float4 w1 = *(const float4*)&Wt[krow][32 + tx * 4];   // cols 8tx+4..+7
                unsigned long long wp[4];
                PACK_F32X2(wp[0], __float_as_uint(w0.x), __float_as_uint(w0.y));
                PACK_F32X2(wp[1], __float_as_uint(w0.z), __float_as_uint(w0.w));
                PACK_F32X2(wp[2], __float_as_uint(w1.x), __float_as_uint(w1.y));
                PACK_F32X2(wp[3], __float_as_uint(w1.z), __float_as_uint(w1.w));
                #pragma unroll
                for (int i = 0; i < 8; i++) {
                    float xs = (j == 0) ? xv[i].x : (j == 1) ? xv[i].y
                             : (j == 2) ? xv[i].z : xv[i].w;
                    unsigned long long xd;
                    PACK_F32X2(xd, __float_as_uint(xs), __float_as_uint(xs));
                    #pragma unroll
                    for (int p = 0; p < 4; p++)
                        FMA_F32X2(acc[i][p], xd, wp[p], acc[i][p]);
                }
            }
        }
    }

    // ---- store: 8 rows x 8 cols per thread ----
    #pragma unroll
    for (int i = 0; i < 8; i++) {
        const int gr = rowbase + ty + 32 * i;
        if (gr < N) {
            unsigned int c0, c1, c2, c3, c4, c5, c6, c7;
            UNPACK_F32X2(c0, c1, acc[i][0]);
            UNPACK_F32X2(c2, c3, acc[i][1]);
            UNPACK_F32X2(c4, c5, acc[i][2]);
            UNPACK_F32X2(c6, c7, acc[i][3]);
            float4 v0 = make_float4(__uint_as_float(c0), __uint_as_float(c1),
                                    __uint_as_float(c2), __uint_as_float(c3));
            float4 v1 = make_float4(__uint_as_float(c4), __uint_as_float(c5),
                                    __uint_as_float(c6), __uint_as_float(c7));
            float* yrow = out + (size_t)gr * 64 + 8 * tx;
            *(float4*)(yrow)     = v0;
            *(float4*)(yrow + 4) = v1;
        }
    }
}

// ---------------------------------------------------------------------------
// Inputs (metadata order):
//   0: x_src f32 [100000*64]   1: x_dst f32 [100000*64]
//   2: edge_index [2*E] (int32 or int64)   3: edge_weight f32 [E]
//   4: W_nei f32 [64*64]   5: W_self f32 [64*64]   6: b_self f32 [64]
// Output: f32 [100000*64]
// ---------------------------------------------------------------------------
extern "C" void kernel_launch(void* const* d_in, const int* in_sizes, int n_in,
                              void* d_out, int out_size)
{
    const float* x_src  = (const float*)d_in[0];
    const float* x_dst  = (const float*)d_in[1];
    const void*  ei     = d_in[2];
    const float* ew     = (const float*)d_in[3];
    const float* W_nei  = (const float*)d_in[4];
    const float* W_self = (const float*)d_in[5];
    const float* b_self = (const float*)d_in[6];
    float*       out    = (float*)d_out;

    const int n_src = in_sizes[0] / 64;
    const int n_dst = in_sizes[1] / 64;
    const int E     = in_sizes[3];

    float* aggp = nullptr;
    cudaGetSymbolAddress((void**)&aggp, g_agg);

    // 0) zero the aggregation buffer + decide edge-index dtype
    cudaMemsetAsync(aggp, 0, (size_t)n_dst * 64 * sizeof(float));
    detect_idx_dtype_kernel<<<1, 32>>>((const long long*)ei, E, n_src);

    // 1) scatter in input space: agg[dst] += x_src[src] * w
    {
        long long groups  = ((long long)E + 3) / 4;
        long long threads = groups * 16;
        int blocks = (int)((threads + 255) / 256);
        scatter_kernel<<<blocks, 256>>>(x_src, ei, ew, E);
    }

    // 2) fused GEMM: out = x_dst @ W_self^T + agg @ W_nei^T + b
    fused_gemm_kernel<<<(n_dst + 255) / 256, 256>>>(
        x_dst, W_self, W_nei, b_self, out, n_dst);
}